// round 1
// baseline (speedup 1.0000x reference)
#include <cuda_runtime.h>
#include <math.h>

#define SUB_KEYS   512
#define KEY_DIM    256
#define VALUE_DIM  512
#define TOPK       32
#define D_MODEL    1024
#define LN_EPS     1e-5f
#define MAX_TOKENS 8192

// ---------------- scratch (device globals: no runtime allocation) ------------
__device__ float g_q  [MAX_TOKENS * 2 * KEY_DIM];   // [T, 512]
__device__ float g_sa [MAX_TOKENS * SUB_KEYS];      // [T, 512]
__device__ float g_sb [MAX_TOKENS * SUB_KEYS];      // [T, 512]
__device__ float g_out[MAX_TOKENS * VALUE_DIM];     // [T, 512]
__device__ float g_y  [MAX_TOKENS * D_MODEL];       // [T, 1024]

// ---------------- generic 128x128x16 SGEMM body -------------------------------
// C[M,N] = A[M,K] (row-major, lda) @ op(B) + bias + resid
//   BT=false : B is [K,N] row-major (ldb = row stride)   -> C += A*B
//   BT=true  : B is [N,K] row-major (ldb = row stride)   -> C += A*B^T
// Grid: (N/128, M/128), 256 threads. All dims must divide (they do here).
template <bool BT>
__device__ __forceinline__ void gemm_body(
    const float* __restrict__ A, const float* __restrict__ B,
    float* __restrict__ C, int K, int lda, int ldb, int ldc,
    const float* __restrict__ bias, const float* __restrict__ resid)
{
    __shared__ float As[16][132];   // transposed: As[k][m]
    __shared__ float Bs[16][132];   // Bs[k][n]

    const int tid = threadIdx.x;
    const int m0  = blockIdx.y * 128;
    const int n0  = blockIdx.x * 128;
    const int tx  = tid & 15;
    const int ty  = tid >> 4;

    float acc[8][8];
#pragma unroll
    for (int i = 0; i < 8; i++)
#pragma unroll
        for (int j = 0; j < 8; j++) acc[i][j] = 0.f;

    const int arow = tid >> 2;        // 0..63
    const int akq  = tid & 3;         // 0..3  (float4 slot along K)
    const int brow = tid >> 5;        // 0..7   (NN only)
    const int bcol = (tid & 31) << 2; // 0..124 (NN only)

    for (int k0 = 0; k0 < K; k0 += 16) {
        // ---- load A tile (transposed into As[k][m]) ----
#pragma unroll
        for (int p = 0; p < 2; p++) {
            int r = arow + p * 64;
            float4 v = *(const float4*)(A + (size_t)(m0 + r) * lda + k0 + akq * 4);
            As[akq * 4 + 0][r] = v.x;
            As[akq * 4 + 1][r] = v.y;
            As[akq * 4 + 2][r] = v.z;
            As[akq * 4 + 3][r] = v.w;
        }
        // ---- load B tile ----
        if (BT) {
            // B[N,K]: same access pattern as A, transposed into Bs[k][n]
#pragma unroll
            for (int p = 0; p < 2; p++) {
                int r = arow + p * 64;  // n index
                float4 v = *(const float4*)(B + (size_t)(n0 + r) * ldb + k0 + akq * 4);
                Bs[akq * 4 + 0][r] = v.x;
                Bs[akq * 4 + 1][r] = v.y;
                Bs[akq * 4 + 2][r] = v.z;
                Bs[akq * 4 + 3][r] = v.w;
            }
        } else {
            // B[K,N]: direct rows
#pragma unroll
            for (int p = 0; p < 2; p++) {
                int r = brow + p * 8;   // k index
                *(float4*)&Bs[r][bcol] =
                    *(const float4*)(B + (size_t)(k0 + r) * ldb + n0 + bcol);
            }
        }
        __syncthreads();

        // ---- 128x128 FFMA micro-kernel ----
#pragma unroll
        for (int k = 0; k < 16; k++) {
            float a[8], b[8];
            *(float4*)(a)     = *(const float4*)&As[k][ty * 4];
            *(float4*)(a + 4) = *(const float4*)&As[k][64 + ty * 4];
            *(float4*)(b)     = *(const float4*)&Bs[k][tx * 4];
            *(float4*)(b + 4) = *(const float4*)&Bs[k][64 + tx * 4];
#pragma unroll
            for (int i = 0; i < 8; i++)
#pragma unroll
                for (int j = 0; j < 8; j++)
                    acc[i][j] = fmaf(a[i], b[j], acc[i][j]);
        }
        __syncthreads();
    }

    // ---- epilogue ----
#pragma unroll
    for (int i = 0; i < 8; i++) {
        int m = m0 + ((i < 4) ? (ty * 4 + i) : (64 + ty * 4 + i - 4));
#pragma unroll
        for (int j = 0; j < 8; j++) {
            int n = n0 + ((j < 4) ? (tx * 4 + j) : (64 + tx * 4 + j - 4));
            float v = acc[i][j];
            if (bias)  v += bias[n];
            if (resid) v += resid[(size_t)m * ldc + n];
            C[(size_t)m * ldc + n] = v;
        }
    }
}

// ---- GEMM instantiations (globals referenced directly; no symbol lookups) ----
__global__ __launch_bounds__(256) void k_gemm_q(
    const float* __restrict__ x, const float* __restrict__ Wq,
    const float* __restrict__ bq)
{
    gemm_body<false>(x, Wq, g_q, D_MODEL, D_MODEL, 2 * KEY_DIM, 2 * KEY_DIM, bq, nullptr);
}

__global__ __launch_bounds__(256) void k_gemm_sa(const float* __restrict__ ca)
{
    gemm_body<true>(g_q, ca, g_sa, KEY_DIM, 2 * KEY_DIM, KEY_DIM, SUB_KEYS, nullptr, nullptr);
}

__global__ __launch_bounds__(256) void k_gemm_sb(const float* __restrict__ cb)
{
    gemm_body<true>(g_q + KEY_DIM, cb, g_sb, KEY_DIM, 2 * KEY_DIM, KEY_DIM, SUB_KEYS, nullptr, nullptr);
}

__global__ __launch_bounds__(256) void k_gemm_y(
    const float* __restrict__ Wo, const float* __restrict__ bo,
    const float* __restrict__ x)
{
    gemm_body<false>(g_out, Wo, g_y, VALUE_DIM, VALUE_DIM, D_MODEL, D_MODEL, bo, x);
}

// ---------------- warp-per-token two-stage top-k + softmax + gather ----------
// 8 warps per block, 1 token per warp. Fully warp-synchronous argmax
// (no block barriers). Tie-break: larger score, then smaller index
// (matches lax.top_k first-occurrence semantics).
__global__ __launch_bounds__(256) void topk_gather_kernel(
    const float* __restrict__ values, int NT)
{
    const int w     = threadIdx.x >> 5;
    const int lane  = threadIdx.x & 31;
    const int token = blockIdx.x * 8 + w;
    if (token >= NT) return;

    __shared__ float s_sa[8][32], s_sb[8][32], s_fs[8][32], s_w[8][32];
    __shared__ int   s_ia[8][32], s_ib[8][32], s_fidx[8][32];

    // ---- stage 1: top-32 of scores_a and scores_b (512 each) ----
#pragma unroll 1
    for (int side = 0; side < 2; side++) {
        const float* sc = (side == 0 ? g_sa : g_sb) + (size_t)token * SUB_KEYS;
        float va[16];
#pragma unroll
        for (int t = 0; t < 16; t++) va[t] = sc[lane + 32 * t];

        for (int it = 0; it < TOPK; it++) {
            float m = -INFINITY; int mi = 0;
#pragma unroll
            for (int t = 0; t < 16; t++)
                if (va[t] > m) { m = va[t]; mi = t; }
            int gi = lane + 32 * mi;
#pragma unroll
            for (int off = 16; off > 0; off >>= 1) {
                float om = __shfl_xor_sync(0xffffffffu, m, off);
                int   og = __shfl_xor_sync(0xffffffffu, gi, off);
                if (om > m || (om == m && og < gi)) { m = om; gi = og; }
            }
            if (lane == 0) {
                if (side == 0) { s_sa[w][it] = m; s_ia[w][it] = gi; }
                else           { s_sb[w][it] = m; s_ib[w][it] = gi; }
            }
            if ((gi & 31) == lane) va[gi >> 5] = -INFINITY;
        }
    }
    __syncwarp();

    // ---- stage 2: top-32 of the 32x32 combined scores ----
    // lane L owns pairs p = L*32 + j (i-rank = L fixed).
    const float saL = s_sa[w][lane];
    unsigned msk = 0;
    for (int it = 0; it < TOPK; it++) {
        float m = -INFINITY; int mj = 0;
#pragma unroll
        for (int j = 0; j < 32; j++) {
            if (!((msk >> j) & 1u)) {
                float s = saL + s_sb[w][j];
                if (s > m) { m = s; mj = j; }
            }
        }
        int pg = lane * 32 + mj;
#pragma unroll
        for (int off = 16; off > 0; off >>= 1) {
            float om = __shfl_xor_sync(0xffffffffu, m, off);
            int   op = __shfl_xor_sync(0xffffffffu, pg, off);
            if (om > m || (om == m && op < pg)) { m = om; pg = op; }
        }
        if (lane == 0) {
            s_fs[w][it]   = m;
            s_fidx[w][it] = s_ia[w][pg >> 5] * SUB_KEYS + s_ib[w][pg & 31];
        }
        if ((pg >> 5) == lane) msk |= 1u << (pg & 31);
    }
    __syncwarp();

    // ---- softmax over the 32 final scores ----
    float f = s_fs[w][lane];
    float mx = f;
#pragma unroll
    for (int off = 16; off > 0; off >>= 1)
        mx = fmaxf(mx, __shfl_xor_sync(0xffffffffu, mx, off));
    float e = expf(f - mx);
    float sum = e;
#pragma unroll
    for (int off = 16; off > 0; off >>= 1)
        sum += __shfl_xor_sync(0xffffffffu, sum, off);
    s_w[w][lane] = e / sum;
    __syncwarp();

    // ---- weighted gather of 32 value rows (512 wide) ----
    float acc[16];
#pragma unroll
    for (int t = 0; t < 16; t++) acc[t] = 0.f;
#pragma unroll 4
    for (int r = 0; r < TOPK; r++) {
        const float wt = s_w[w][r];
        const float* vr = values + (size_t)s_fidx[w][r] * VALUE_DIM;
#pragma unroll
        for (int t = 0; t < 16; t++)
            acc[t] = fmaf(wt, vr[lane + 32 * t], acc[t]);
    }
    float* o = g_out + (size_t)token * VALUE_DIM;
#pragma unroll
    for (int t = 0; t < 16; t++) o[lane + 32 * t] = acc[t];
}

// ---------------- LayerNorm: one block per row, D=1024 ------------------------
__global__ __launch_bounds__(256) void ln_kernel(
    const float* __restrict__ gamma, const float* __restrict__ beta,
    float* __restrict__ out)
{
    const int row = blockIdx.x;
    const int tid = threadIdx.x;
    const float* yr = g_y + (size_t)row * D_MODEL;

    float v[4];
    float s = 0.f, ss = 0.f;
#pragma unroll
    for (int j = 0; j < 4; j++) {
        v[j] = yr[tid + 256 * j];
        s  += v[j];
        ss += v[j] * v[j];
    }
#pragma unroll
    for (int off = 16; off > 0; off >>= 1) {
        s  += __shfl_xor_sync(0xffffffffu, s,  off);
        ss += __shfl_xor_sync(0xffffffffu, ss, off);
    }
    __shared__ float red_s[8], red_ss[8];
    __shared__ float s_mu, s_rstd;
    const int wid = tid >> 5, lane = tid & 31;
    if (lane == 0) { red_s[wid] = s; red_ss[wid] = ss; }
    __syncthreads();
    if (tid == 0) {
        float S = 0.f, SS = 0.f;
#pragma unroll
        for (int i = 0; i < 8; i++) { S += red_s[i]; SS += red_ss[i]; }
        float mu  = S * (1.f / D_MODEL);
        float var = SS * (1.f / D_MODEL) - mu * mu;
        s_mu = mu;
        s_rstd = rsqrtf(var + LN_EPS);
    }
    __syncthreads();
    const float mu = s_mu, rstd = s_rstd;
    float* orow = out + (size_t)row * D_MODEL;
#pragma unroll
    for (int j = 0; j < 4; j++) {
        int c = tid + 256 * j;
        orow[c] = (v[j] - mu) * rstd * gamma[c] + beta[c];
    }
}

// ---------------- launch -----------------------------------------------------
extern "C" void kernel_launch(void* const* d_in, const int* in_sizes, int n_in,
                              void* d_out, int out_size)
{
    const float* x      = (const float*)d_in[0];
    const float* Wq     = (const float*)d_in[1];
    const float* bq     = (const float*)d_in[2];
    const float* ca     = (const float*)d_in[3];
    const float* cb     = (const float*)d_in[4];
    const float* values = (const float*)d_in[5];
    const float* Wo     = (const float*)d_in[6];
    const float* bo     = (const float*)d_in[7];
    const float* gamma  = (const float*)d_in[8];
    const float* beta   = (const float*)d_in[9];
    float* out = (float*)d_out;

    const int NT = in_sizes[0] / D_MODEL;   // 8192 tokens

    dim3 thr(256);

    // q = x @ Wq + bq                      [NT, 512]
    k_gemm_q<<<dim3(2 * KEY_DIM / 128, NT / 128), thr>>>(x, Wq, bq);
    // scores_a = qa @ Ca^T, scores_b = qb @ Cb^T   [NT, 512] each
    k_gemm_sa<<<dim3(SUB_KEYS / 128, NT / 128), thr>>>(ca);
    k_gemm_sb<<<dim3(SUB_KEYS / 128, NT / 128), thr>>>(cb);
    // two-stage top-k + softmax + weighted value gather -> g_out [NT, 512]
    topk_gather_kernel<<<dim3((NT + 7) / 8), thr>>>(values, NT);
    // y = x + g_out @ Wo + bo              [NT, 1024]
    k_gemm_y<<<dim3(D_MODEL / 128, NT / 128), thr>>>(Wo, bo, x);
    // LayerNorm -> d_out
    ln_kernel<<<dim3(NT), thr>>>(gamma, beta, out);
}

// round 2
// speedup vs baseline: 1.0025x; 1.0025x over previous
#include <cuda_runtime.h>
#include <math.h>

#define SUB_KEYS   512
#define KEY_DIM    256
#define VALUE_DIM  512
#define TOPK       32
#define D_MODEL    1024
#define LN_EPS     1e-5f
#define MAX_TOKENS 8192

// ---------------- scratch (device globals: no runtime allocation) ------------
__device__ float g_q  [MAX_TOKENS * 2 * KEY_DIM];   // [T, 512]
__device__ float g_sa [MAX_TOKENS * SUB_KEYS];      // [T, 512]
__device__ float g_sb [MAX_TOKENS * SUB_KEYS];      // [T, 512]
__device__ float g_out[MAX_TOKENS * VALUE_DIM];     // [T, 512]
__device__ float g_y  [MAX_TOKENS * D_MODEL];       // [T, 1024]

// ---------------- generic 128x128x16 SGEMM body -------------------------------
// C[M,N] = A[M,K] (row-major, lda) @ op(B) + bias + resid
//   BT=false : B is [K,N] row-major (ldb = row stride)   -> C += A*B
//   BT=true  : B is [N,K] row-major (ldb = row stride)   -> C += A*B^T
// Grid: (N/128, M/128), 256 threads. All dims must divide (they do here).
template <bool BT>
__device__ __forceinline__ void gemm_body(
    const float* __restrict__ A, const float* __restrict__ B,
    float* __restrict__ C, int K, int lda, int ldb, int ldc,
    const float* __restrict__ bias, const float* __restrict__ resid)
{
    __shared__ float As[16][132];   // transposed: As[k][m]
    __shared__ float Bs[16][132];   // Bs[k][n]

    const int tid = threadIdx.x;
    const int m0  = blockIdx.y * 128;
    const int n0  = blockIdx.x * 128;
    const int tx  = tid & 15;
    const int ty  = tid >> 4;

    float acc[8][8];
#pragma unroll
    for (int i = 0; i < 8; i++)
#pragma unroll
        for (int j = 0; j < 8; j++) acc[i][j] = 0.f;

    const int arow = tid >> 2;        // 0..63
    const int akq  = tid & 3;         // 0..3  (float4 slot along K)
    const int brow = tid >> 5;        // 0..7   (NN only)
    const int bcol = (tid & 31) << 2; // 0..124 (NN only)

    for (int k0 = 0; k0 < K; k0 += 16) {
        // ---- load A tile (transposed into As[k][m]) ----
#pragma unroll
        for (int p = 0; p < 2; p++) {
            int r = arow + p * 64;
            float4 v = *(const float4*)(A + (size_t)(m0 + r) * lda + k0 + akq * 4);
            As[akq * 4 + 0][r] = v.x;
            As[akq * 4 + 1][r] = v.y;
            As[akq * 4 + 2][r] = v.z;
            As[akq * 4 + 3][r] = v.w;
        }
        // ---- load B tile ----
        if (BT) {
            // B[N,K]: same access pattern as A, transposed into Bs[k][n]
#pragma unroll
            for (int p = 0; p < 2; p++) {
                int r = arow + p * 64;  // n index
                float4 v = *(const float4*)(B + (size_t)(n0 + r) * ldb + k0 + akq * 4);
                Bs[akq * 4 + 0][r] = v.x;
                Bs[akq * 4 + 1][r] = v.y;
                Bs[akq * 4 + 2][r] = v.z;
                Bs[akq * 4 + 3][r] = v.w;
            }
        } else {
            // B[K,N]: direct rows
#pragma unroll
            for (int p = 0; p < 2; p++) {
                int r = brow + p * 8;   // k index
                *(float4*)&Bs[r][bcol] =
                    *(const float4*)(B + (size_t)(k0 + r) * ldb + n0 + bcol);
            }
        }
        __syncthreads();

        // ---- 128x128 FFMA micro-kernel ----
#pragma unroll
        for (int k = 0; k < 16; k++) {
            float a[8], b[8];
            *(float4*)(a)     = *(const float4*)&As[k][ty * 4];
            *(float4*)(a + 4) = *(const float4*)&As[k][64 + ty * 4];
            *(float4*)(b)     = *(const float4*)&Bs[k][tx * 4];
            *(float4*)(b + 4) = *(const float4*)&Bs[k][64 + tx * 4];
#pragma unroll
            for (int i = 0; i < 8; i++)
#pragma unroll
                for (int j = 0; j < 8; j++)
                    acc[i][j] = fmaf(a[i], b[j], acc[i][j]);
        }
        __syncthreads();
    }

    // ---- epilogue ----
#pragma unroll
    for (int i = 0; i < 8; i++) {
        int m = m0 + ((i < 4) ? (ty * 4 + i) : (64 + ty * 4 + i - 4));
#pragma unroll
        for (int j = 0; j < 8; j++) {
            int n = n0 + ((j < 4) ? (tx * 4 + j) : (64 + tx * 4 + j - 4));
            float v = acc[i][j];
            if (bias)  v += bias[n];
            if (resid) v += resid[(size_t)m * ldc + n];
            C[(size_t)m * ldc + n] = v;
        }
    }
}

// ---- GEMM instantiations (globals referenced directly; no symbol lookups) ----
__global__ __launch_bounds__(256) void k_gemm_q(
    const float* __restrict__ x, const float* __restrict__ Wq,
    const float* __restrict__ bq)
{
    gemm_body<false>(x, Wq, g_q, D_MODEL, D_MODEL, 2 * KEY_DIM, 2 * KEY_DIM, bq, nullptr);
}

__global__ __launch_bounds__(256) void k_gemm_sa(const float* __restrict__ ca)
{
    gemm_body<true>(g_q, ca, g_sa, KEY_DIM, 2 * KEY_DIM, KEY_DIM, SUB_KEYS, nullptr, nullptr);
}

__global__ __launch_bounds__(256) void k_gemm_sb(const float* __restrict__ cb)
{
    gemm_body<true>(g_q + KEY_DIM, cb, g_sb, KEY_DIM, 2 * KEY_DIM, KEY_DIM, SUB_KEYS, nullptr, nullptr);
}

__global__ __launch_bounds__(256) void k_gemm_y(
    const float* __restrict__ Wo, const float* __restrict__ bo,
    const float* __restrict__ x)
{
    gemm_body<false>(g_out, Wo, g_y, VALUE_DIM, VALUE_DIM, D_MODEL, D_MODEL, bo, x);
}

// ---------------- warp-per-token two-stage top-k + softmax + gather ----------
// 8 warps per block, 1 token per warp. Fully warp-synchronous argmax
// (no block barriers). Tie-break: larger score, then smaller index
// (matches lax.top_k first-occurrence semantics).
__global__ __launch_bounds__(256) void topk_gather_kernel(
    const float* __restrict__ values, int NT)
{
    const int w     = threadIdx.x >> 5;
    const int lane  = threadIdx.x & 31;
    const int token = blockIdx.x * 8 + w;
    if (token >= NT) return;

    __shared__ float s_sa[8][32], s_sb[8][32], s_fs[8][32], s_w[8][32];
    __shared__ int   s_ia[8][32], s_ib[8][32], s_fidx[8][32];

    // ---- stage 1: top-32 of scores_a and scores_b (512 each) ----
#pragma unroll 1
    for (int side = 0; side < 2; side++) {
        const float* sc = (side == 0 ? g_sa : g_sb) + (size_t)token * SUB_KEYS;
        float va[16];
#pragma unroll
        for (int t = 0; t < 16; t++) va[t] = sc[lane + 32 * t];

        for (int it = 0; it < TOPK; it++) {
            float m = -INFINITY; int mi = 0;
#pragma unroll
            for (int t = 0; t < 16; t++)
                if (va[t] > m) { m = va[t]; mi = t; }
            int gi = lane + 32 * mi;
#pragma unroll
            for (int off = 16; off > 0; off >>= 1) {
                float om = __shfl_xor_sync(0xffffffffu, m, off);
                int   og = __shfl_xor_sync(0xffffffffu, gi, off);
                if (om > m || (om == m && og < gi)) { m = om; gi = og; }
            }
            if (lane == 0) {
                if (side == 0) { s_sa[w][it] = m; s_ia[w][it] = gi; }
                else           { s_sb[w][it] = m; s_ib[w][it] = gi; }
            }
            if ((gi & 31) == lane) va[gi >> 5] = -INFINITY;
        }
    }
    __syncwarp();

    // ---- stage 2: top-32 of the 32x32 combined scores ----
    // lane L owns pairs p = L*32 + j (i-rank = L fixed).
    const float saL = s_sa[w][lane];
    unsigned msk = 0;
    for (int it = 0; it < TOPK; it++) {
        float m = -INFINITY; int mj = 0;
#pragma unroll
        for (int j = 0; j < 32; j++) {
            if (!((msk >> j) & 1u)) {
                float s = saL + s_sb[w][j];
                if (s > m) { m = s; mj = j; }
            }
        }
        int pg = lane * 32 + mj;
#pragma unroll
        for (int off = 16; off > 0; off >>= 1) {
            float om = __shfl_xor_sync(0xffffffffu, m, off);
            int   op = __shfl_xor_sync(0xffffffffu, pg, off);
            if (om > m || (om == m && op < pg)) { m = om; pg = op; }
        }
        if (lane == 0) {
            s_fs[w][it]   = m;
            s_fidx[w][it] = s_ia[w][pg >> 5] * SUB_KEYS + s_ib[w][pg & 31];
        }
        if ((pg >> 5) == lane) msk |= 1u << (pg & 31);
    }
    __syncwarp();

    // ---- softmax over the 32 final scores ----
    float f = s_fs[w][lane];
    float mx = f;
#pragma unroll
    for (int off = 16; off > 0; off >>= 1)
        mx = fmaxf(mx, __shfl_xor_sync(0xffffffffu, mx, off));
    float e = expf(f - mx);
    float sum = e;
#pragma unroll
    for (int off = 16; off > 0; off >>= 1)
        sum += __shfl_xor_sync(0xffffffffu, sum, off);
    s_w[w][lane] = e / sum;
    __syncwarp();

    // ---- weighted gather of 32 value rows (512 wide) ----
    float acc[16];
#pragma unroll
    for (int t = 0; t < 16; t++) acc[t] = 0.f;
#pragma unroll 4
    for (int r = 0; r < TOPK; r++) {
        const float wt = s_w[w][r];
        const float* vr = values + (size_t)s_fidx[w][r] * VALUE_DIM;
#pragma unroll
        for (int t = 0; t < 16; t++)
            acc[t] = fmaf(wt, vr[lane + 32 * t], acc[t]);
    }
    float* o = g_out + (size_t)token * VALUE_DIM;
#pragma unroll
    for (int t = 0; t < 16; t++) o[lane + 32 * t] = acc[t];
}

// ---------------- LayerNorm: one block per row, D=1024 ------------------------
__global__ __launch_bounds__(256) void ln_kernel(
    const float* __restrict__ gamma, const float* __restrict__ beta,
    float* __restrict__ out)
{
    const int row = blockIdx.x;
    const int tid = threadIdx.x;
    const float* yr = g_y + (size_t)row * D_MODEL;

    float v[4];
    float s = 0.f, ss = 0.f;
#pragma unroll
    for (int j = 0; j < 4; j++) {
        v[j] = yr[tid + 256 * j];
        s  += v[j];
        ss += v[j] * v[j];
    }
#pragma unroll
    for (int off = 16; off > 0; off >>= 1) {
        s  += __shfl_xor_sync(0xffffffffu, s,  off);
        ss += __shfl_xor_sync(0xffffffffu, ss, off);
    }
    __shared__ float red_s[8], red_ss[8];
    __shared__ float s_mu, s_rstd;
    const int wid = tid >> 5, lane = tid & 31;
    if (lane == 0) { red_s[wid] = s; red_ss[wid] = ss; }
    __syncthreads();
    if (tid == 0) {
        float S = 0.f, SS = 0.f;
#pragma unroll
        for (int i = 0; i < 8; i++) { S += red_s[i]; SS += red_ss[i]; }
        float mu  = S * (1.f / D_MODEL);
        float var = SS * (1.f / D_MODEL) - mu * mu;
        s_mu = mu;
        s_rstd = rsqrtf(var + LN_EPS);
    }
    __syncthreads();
    const float mu = s_mu, rstd = s_rstd;
    float* orow = out + (size_t)row * D_MODEL;
#pragma unroll
    for (int j = 0; j < 4; j++) {
        int c = tid + 256 * j;
        orow[c] = (v[j] - mu) * rstd * gamma[c] + beta[c];
    }
}

// ---------------- launch -----------------------------------------------------
extern "C" void kernel_launch(void* const* d_in, const int* in_sizes, int n_in,
                              void* d_out, int out_size)
{
    const float* x      = (const float*)d_in[0];
    const float* Wq     = (const float*)d_in[1];
    const float* bq     = (const float*)d_in[2];
    const float* ca     = (const float*)d_in[3];
    const float* cb     = (const float*)d_in[4];
    const float* values = (const float*)d_in[5];
    const float* Wo     = (const float*)d_in[6];
    const float* bo     = (const float*)d_in[7];
    const float* gamma  = (const float*)d_in[8];
    const float* beta   = (const float*)d_in[9];
    float* out = (float*)d_out;

    const int NT = in_sizes[0] / D_MODEL;   // 8192 tokens

    dim3 thr(256);

    // q = x @ Wq + bq                      [NT, 512]
    k_gemm_q<<<dim3(2 * KEY_DIM / 128, NT / 128), thr>>>(x, Wq, bq);
    // scores_a = qa @ Ca^T, scores_b = qb @ Cb^T   [NT, 512] each
    k_gemm_sa<<<dim3(SUB_KEYS / 128, NT / 128), thr>>>(ca);
    k_gemm_sb<<<dim3(SUB_KEYS / 128, NT / 128), thr>>>(cb);
    // two-stage top-k + softmax + weighted value gather -> g_out [NT, 512]
    topk_gather_kernel<<<dim3((NT + 7) / 8), thr>>>(values, NT);
    // y = x + g_out @ Wo + bo              [NT, 1024]
    k_gemm_y<<<dim3(D_MODEL / 128, NT / 128), thr>>>(Wo, bo, x);
    // LayerNorm -> d_out
    ln_kernel<<<dim3(NT), thr>>>(gamma, beta, out);
}

// round 5
// speedup vs baseline: 2.5701x; 2.5637x over previous
#include <cuda_runtime.h>
#include <cuda_bf16.h>
#include <math.h>
#include <stdint.h>

#define SUB_KEYS   512
#define KEY_DIM    256
#define VALUE_DIM  512
#define TOPK       32
#define D_MODEL    1024
#define LN_EPS     1e-5f
#define MAX_TOKENS 8192

typedef unsigned long long u64;
typedef unsigned int u32;

// ---------------- scratch (device globals) ------------------------------------
__device__ __nv_bfloat16 g_xh  [MAX_TOKENS * D_MODEL];
__device__ __nv_bfloat16 g_wqT [2 * KEY_DIM * D_MODEL];   // [512,1024]
__device__ __nv_bfloat16 g_cah [SUB_KEYS * KEY_DIM];
__device__ __nv_bfloat16 g_cbh [SUB_KEYS * KEY_DIM];
__device__ __nv_bfloat16 g_woT [D_MODEL * VALUE_DIM];     // [1024,512]
__device__ __nv_bfloat16 g_qh  [MAX_TOKENS * 2 * KEY_DIM];
__device__ __nv_bfloat16 g_outh[MAX_TOKENS * VALUE_DIM];
__device__ float g_sa[MAX_TOKENS * SUB_KEYS];
__device__ float g_sb[MAX_TOKENS * SUB_KEYS];
__device__ float g_y [MAX_TOKENS * D_MODEL];

__device__ __forceinline__ u32 smem_u32(const void* p) {
    return (u32)__cvta_generic_to_shared(p);
}

// ---------------- portable tensor-core GEMM (mma.sync bf16) -------------------
// C[M,N] = A[M,K](row-major bf16) @ B[N,K](row-major bf16)^T  (+bias +resid)
// Block 128x128, K-tile 32, 256 threads (8 warps as 4x2), cp.async 2-stage.
#define BM 128
#define BN 128
#define BK 32
#define APAD 40   // row stride in elements (80B: conflict-free LDSM, odd*16B)

__device__ __forceinline__ void cp16(u32 saddr, const void* g) {
    asm volatile("cp.async.cg.shared.global [%0], [%1], 16;" :: "r"(saddr), "l"(g));
}
__device__ __forceinline__ void cp_commit() { asm volatile("cp.async.commit_group;"); }
template <int N> __device__ __forceinline__ void cp_wait() {
    asm volatile("cp.async.wait_group %0;" :: "n"(N));
}
__device__ __forceinline__ void ldsm4(u32& r0, u32& r1, u32& r2, u32& r3, u32 a) {
    asm volatile("ldmatrix.sync.aligned.m8n8.x4.shared.b16 {%0,%1,%2,%3}, [%4];"
                 : "=r"(r0), "=r"(r1), "=r"(r2), "=r"(r3) : "r"(a));
}
__device__ __forceinline__ void mma16816(float* d, const u32* a, u32 b0, u32 b1) {
    asm volatile(
        "mma.sync.aligned.m16n8k16.row.col.f32.bf16.bf16.f32 "
        "{%0,%1,%2,%3}, {%4,%5,%6,%7}, {%8,%9}, {%0,%1,%2,%3};"
        : "+f"(d[0]), "+f"(d[1]), "+f"(d[2]), "+f"(d[3])
        : "r"(a[0]), "r"(a[1]), "r"(a[2]), "r"(a[3]), "r"(b0), "r"(b1));
}

template <bool OB, bool HB, bool HR>
__device__ __forceinline__ void gemm_mma_body(
    const __nv_bfloat16* __restrict__ A, int lda,
    const __nv_bfloat16* __restrict__ B, int ldb,
    void* __restrict__ Cv, int ldc, int K,
    const float* __restrict__ bias, const float* __restrict__ resid)
{
    __shared__ __nv_bfloat16 sA[2][BM][APAD];
    __shared__ __nv_bfloat16 sB[2][BN][APAD];

    const int t = threadIdx.x;
    const int wid = t >> 5, lane = t & 31;
    const int wm = wid >> 1;          // 0..3 : 32-row slab
    const int wn = wid & 1;           // 0..1 : 64-col slab
    const int m0 = blockIdx.y * BM, n0 = blockIdx.x * BN;

    // cp.async mapping: 1024 16B-chunks per (A,B) tile, 256 threads x {id, id+256}
    const int r1 = t >> 2,        kc1 = t & 3;          // chunk id = t
    const int r2 = (t + 256) >> 2, kc2 = t & 3;         // chunk id = t+256

    const int nct = K / BK;

    // ---- preload tile 0 ----
    {
        const __nv_bfloat16* Ag = A + (size_t)m0 * lda;
        const __nv_bfloat16* Bg = B + (size_t)n0 * ldb;
        cp16(smem_u32(&sA[0][r1][kc1 * 8]), Ag + (size_t)r1 * lda + kc1 * 8);
        cp16(smem_u32(&sA[0][r2][kc2 * 8]), Ag + (size_t)r2 * lda + kc2 * 8);
        cp16(smem_u32(&sB[0][r1][kc1 * 8]), Bg + (size_t)r1 * ldb + kc1 * 8);
        cp16(smem_u32(&sB[0][r2][kc2 * 8]), Bg + (size_t)r2 * ldb + kc2 * 8);
        cp_commit();
    }

    float acc[2][8][4];
#pragma unroll
    for (int i = 0; i < 2; i++)
#pragma unroll
        for (int j = 0; j < 8; j++)
#pragma unroll
            for (int q = 0; q < 4; q++) acc[i][j][q] = 0.f;

    // ldmatrix lane addressing (constant per thread)
    const int a_row = (lane & 15);
    const int a_col = (lane >> 4) << 3;
    const int b_row = ((lane >> 4) << 3) + (lane & 7);
    const int b_col = (lane & 8) ? 8 : 0;

    for (int c = 0; c < nct; c++) {
        const int buf = c & 1;
        if (c + 1 < nct) {
            const int nb = buf ^ 1;
            const __nv_bfloat16* Ag = A + (size_t)m0 * lda + (c + 1) * BK;
            const __nv_bfloat16* Bg = B + (size_t)n0 * ldb + (c + 1) * BK;
            cp16(smem_u32(&sA[nb][r1][kc1 * 8]), Ag + (size_t)r1 * lda + kc1 * 8);
            cp16(smem_u32(&sA[nb][r2][kc2 * 8]), Ag + (size_t)r2 * lda + kc2 * 8);
            cp16(smem_u32(&sB[nb][r1][kc1 * 8]), Bg + (size_t)r1 * ldb + kc1 * 8);
            cp16(smem_u32(&sB[nb][r2][kc2 * 8]), Bg + (size_t)r2 * ldb + kc2 * 8);
            cp_commit();
            cp_wait<1>();
        } else {
            cp_wait<0>();
        }
        __syncthreads();

#pragma unroll
        for (int ks = 0; ks < 2; ks++) {
            u32 afr[2][4];
#pragma unroll
            for (int mt = 0; mt < 2; mt++)
                ldsm4(afr[mt][0], afr[mt][1], afr[mt][2], afr[mt][3],
                      smem_u32(&sA[buf][wm * 32 + mt * 16 + a_row][ks * 16 + a_col]));
            u32 bfr[4][4];
#pragma unroll
            for (int p = 0; p < 4; p++)
                ldsm4(bfr[p][0], bfr[p][1], bfr[p][2], bfr[p][3],
                      smem_u32(&sB[buf][wn * 64 + p * 16 + b_row][ks * 16 + b_col]));
#pragma unroll
            for (int mt = 0; mt < 2; mt++)
#pragma unroll
                for (int p = 0; p < 4; p++) {
                    mma16816(acc[mt][p * 2 + 0], afr[mt], bfr[p][0], bfr[p][1]);
                    mma16816(acc[mt][p * 2 + 1], afr[mt], bfr[p][2], bfr[p][3]);
                }
        }
        __syncthreads();
    }

    // ---- epilogue ----
    const int gp = lane >> 2, tg = lane & 3;
#pragma unroll
    for (int mt = 0; mt < 2; mt++) {
#pragma unroll
        for (int half = 0; half < 2; half++) {
            const int m = m0 + wm * 32 + mt * 16 + gp + half * 8;
#pragma unroll
            for (int nt = 0; nt < 8; nt++) {
                const int n = n0 + wn * 64 + nt * 8 + tg * 2;
                float v0 = acc[mt][nt][half * 2 + 0];
                float v1 = acc[mt][nt][half * 2 + 1];
                if (HB) { v0 += bias[n]; v1 += bias[n + 1]; }
                if (HR) {
                    const float2 r = *(const float2*)(resid + (size_t)m * ldc + n);
                    v0 += r.x; v1 += r.y;
                }
                if (OB) {
                    *(__nv_bfloat162*)((__nv_bfloat16*)Cv + (size_t)m * ldc + n) =
                        __floats2bfloat162_rn(v0, v1);
                } else {
                    *(float2*)((float*)Cv + (size_t)m * ldc + n) = make_float2(v0, v1);
                }
            }
        }
    }
}

__global__ __launch_bounds__(256) void k_gemm_q(const float* __restrict__ bq) {
    gemm_mma_body<true, true, false>(g_xh, D_MODEL, g_wqT, D_MODEL, g_qh,
                                     2 * KEY_DIM, D_MODEL, bq, nullptr);
}
__global__ __launch_bounds__(256) void k_gemm_sa() {
    gemm_mma_body<false, false, false>(g_qh, 2 * KEY_DIM, g_cah, KEY_DIM, g_sa,
                                       SUB_KEYS, KEY_DIM, nullptr, nullptr);
}
__global__ __launch_bounds__(256) void k_gemm_sb() {
    gemm_mma_body<false, false, false>(g_qh + KEY_DIM, 2 * KEY_DIM, g_cbh, KEY_DIM, g_sb,
                                       SUB_KEYS, KEY_DIM, nullptr, nullptr);
}
__global__ __launch_bounds__(256) void k_gemm_y(const float* __restrict__ bo,
                                                const float* __restrict__ x) {
    gemm_mma_body<false, true, true>(g_outh, VALUE_DIM, g_woT, VALUE_DIM, g_y,
                                     D_MODEL, VALUE_DIM, bo, x);
}

// ---------------- conversion / transpose --------------------------------------
__global__ void k_cvt(const float* __restrict__ s, __nv_bfloat16* __restrict__ d, int n) {
    int i = (blockIdx.x * blockDim.x + threadIdx.x) * 8;
    if (i < n) {
        float4 a = *(const float4*)(s + i), b = *(const float4*)(s + i + 4);
        __nv_bfloat162 h[4];
        h[0] = __float22bfloat162_rn(make_float2(a.x, a.y));
        h[1] = __float22bfloat162_rn(make_float2(a.z, a.w));
        h[2] = __float22bfloat162_rn(make_float2(b.x, b.y));
        h[3] = __float22bfloat162_rn(make_float2(b.z, b.w));
        *(uint4*)(d + i) = *(uint4*)h;
    }
}
// src [R,C] fp32 -> dst [C,R] bf16 ; block (32,8), grid (C/32, R/32)
__global__ void k_tr(const float* __restrict__ s, __nv_bfloat16* __restrict__ d,
                     int R, int C) {
    __shared__ float tile[32][33];
    int bx = blockIdx.x * 32, by = blockIdx.y * 32;
#pragma unroll
    for (int j = 0; j < 32; j += 8)
        tile[threadIdx.y + j][threadIdx.x] =
            s[(size_t)(by + threadIdx.y + j) * C + bx + threadIdx.x];
    __syncthreads();
#pragma unroll
    for (int j = 0; j < 32; j += 8)
        d[(size_t)(bx + threadIdx.y + j) * R + by + threadIdx.x] =
            __float2bfloat16(tile[threadIdx.x][threadIdx.y + j]);
}

// ---------------- top-k -------------------------------------------------------
__constant__ unsigned char c_ci[128] = {
    0,0,0,0,0,0,0,0,0,0,0,0,0,0,0,0,0,0,0,0,0,0,0,0,0,0,0,0,0,0,0,0,
    1,1,1,1,1,1,1,1,1,1,1,1,1,1,1,1,
    2,2,2,2,2,2,2,2,2,2, 3,3,3,3,3,3,3,3, 4,4,4,4,4,4, 5,5,5,5,5,
    6,6,6,6, 7,7,7,7, 8,8,8, 9,9,9, 10,10, 11,11, 12,12, 13,13, 14,14, 15,15,
    16,17,18,19,20,21,22,23,24,25,26,27,28,29,30,31, 0,0,0,0,0,0,0,0,0};
__constant__ unsigned char c_cj[128] = {
    0,1,2,3,4,5,6,7,8,9,10,11,12,13,14,15,16,17,18,19,20,21,22,23,24,25,26,27,28,29,30,31,
    0,1,2,3,4,5,6,7,8,9,10,11,12,13,14,15,
    0,1,2,3,4,5,6,7,8,9, 0,1,2,3,4,5,6,7, 0,1,2,3,4,5, 0,1,2,3,4,
    0,1,2,3, 0,1,2,3, 0,1,2, 0,1,2, 0,1, 0,1, 0,1, 0,1, 0,1, 0,1,
    0,0,0,0,0,0,0,0,0,0,0,0,0,0,0,0, 0,0,0,0,0,0,0,0,0};

__device__ __forceinline__ u32 fsort(float f) {
    u32 b = __float_as_uint(f);
    return b ^ ((b & 0x80000000u) ? 0xFFFFFFFFu : 0x80000000u);
}
__device__ __forceinline__ float funsort(u32 u) {
    return __uint_as_float((u & 0x80000000u) ? (u ^ 0x80000000u) : ~u);
}
__device__ __forceinline__ u64 shflx64(u64 v, int off) {
    return __shfl_xor_sync(0xffffffffu, v, off);
}

__global__ __launch_bounds__(256) void topk_gather_kernel(
    const float* __restrict__ values, int NT)
{
    const int w = threadIdx.x >> 5, lane = threadIdx.x & 31;
    const int token = blockIdx.x * 8 + w;
    if (token >= NT) return;

    __shared__ float s_av[8][32], s_bv[8][32], s_fs[8][32], s_w[8][32];
    __shared__ int   s_ai[8][32], s_bi[8][32], s_fi[8][32];

    // ---- stage 1: exact top-32 of each 512-score side ----
#pragma unroll 1
    for (int side = 0; side < 2; side++) {
        const float* sc = (side == 0 ? g_sa : g_sb) + (size_t)token * SUB_KEYS;
        u64 key[16];
#pragma unroll
        for (int v = 0; v < 4; v++) {
            float4 f = *(const float4*)(sc + lane * 16 + v * 4);
            int b = lane * 16 + v * 4;
            key[v*4+0] = ((u64)fsort(f.x) << 16) | (u32)(0xFFFF - (b+0));
            key[v*4+1] = ((u64)fsort(f.y) << 16) | (u32)(0xFFFF - (b+1));
            key[v*4+2] = ((u64)fsort(f.z) << 16) | (u32)(0xFFFF - (b+2));
            key[v*4+3] = ((u64)fsort(f.w) << 16) | (u32)(0xFFFF - (b+3));
        }
        // per-lane bitonic sort, descending (static indices: no spill)
#pragma unroll
        for (int size = 2; size <= 16; size <<= 1)
#pragma unroll
            for (int stride = size >> 1; stride > 0; stride >>= 1)
#pragma unroll
                for (int i = 0; i < 16; i++) {
                    int j = i ^ stride;
                    if (j > i) {
                        bool dir = ((i & size) == 0);
                        u64 a = key[i], b = key[j];
                        bool sw = dir ? (a < b) : (a > b);
                        key[i] = sw ? b : a;
                        key[j] = sw ? a : b;
                    }
                }
        // 32 pops: warp max of per-lane heads, winner shifts its list
        for (int it = 0; it < TOPK; it++) {
            u64 m = key[0];
#pragma unroll
            for (int off = 16; off > 0; off >>= 1) {
                u64 o = shflx64(m, off);
                if (o > m) m = o;
            }
            if (key[0] == m) {
#pragma unroll
                for (int q = 0; q < 15; q++) key[q] = key[q + 1];
                key[15] = 0;
            }
            if (lane == it) {
                int idx = 0xFFFF - (int)(m & 0xFFFFu);
                float fv = funsort((u32)(m >> 16));
                if (side == 0) { s_av[w][it] = fv; s_ai[w][it] = idx; }
                else           { s_bv[w][it] = fv; s_bi[w][it] = idx; }
            }
        }
    }
    __syncwarp();

    // ---- stage 2: top-32 of cartesian sums via dominance prune (119 cands) ----
    u64 ck[4];
#pragma unroll
    for (int s = 0; s < 4; s++) {
        int c = lane * 4 + s;
        int i = c_ci[c], j = c_cj[c];
        float sum = s_av[w][i] + s_bv[w][j];
        ck[s] = (c < 119) ? (((u64)fsort(sum) << 16) | (u32)(0xFFFF - (i * 32 + j))) : 0ull;
    }
    for (int it = 0; it < TOPK; it++) {
        u64 m = ck[0];
#pragma unroll
        for (int s = 1; s < 4; s++) if (ck[s] > m) m = ck[s];
#pragma unroll
        for (int off = 16; off > 0; off >>= 1) {
            u64 o = shflx64(m, off);
            if (o > m) m = o;
        }
#pragma unroll
        for (int s = 0; s < 4; s++) if (ck[s] == m) ck[s] = 0;
        if (lane == it) {
            int pp = 0xFFFF - (int)(m & 0xFFFFu);
            s_fs[w][it] = funsort((u32)(m >> 16));
            s_fi[w][it] = s_ai[w][pp >> 5] * SUB_KEYS + s_bi[w][pp & 31];
        }
    }
    __syncwarp();

    // ---- softmax ----
    float f = s_fs[w][lane];
    float mx = f;
#pragma unroll
    for (int off = 16; off > 0; off >>= 1)
        mx = fmaxf(mx, __shfl_xor_sync(0xffffffffu, mx, off));
    float e = expf(f - mx);
    float sum = e;
#pragma unroll
    for (int off = 16; off > 0; off >>= 1)
        sum += __shfl_xor_sync(0xffffffffu, sum, off);
    s_w[w][lane] = e / sum;
    __syncwarp();

    // ---- weighted gather (LDG.128, 2KB rows) ----
    float4 a0 = {0,0,0,0}, a1 = {0,0,0,0}, a2 = {0,0,0,0}, a3 = {0,0,0,0};
#pragma unroll 4
    for (int r = 0; r < TOPK; r++) {
        const float wt = s_w[w][r];
        const float4* vr = (const float4*)(values + (size_t)s_fi[w][r] * VALUE_DIM) + lane * 4;
        float4 v0 = vr[0], v1 = vr[1], v2 = vr[2], v3 = vr[3];
        a0.x = fmaf(wt, v0.x, a0.x); a0.y = fmaf(wt, v0.y, a0.y);
        a0.z = fmaf(wt, v0.z, a0.z); a0.w = fmaf(wt, v0.w, a0.w);
        a1.x = fmaf(wt, v1.x, a1.x); a1.y = fmaf(wt, v1.y, a1.y);
        a1.z = fmaf(wt, v1.z, a1.z); a1.w = fmaf(wt, v1.w, a1.w);
        a2.x = fmaf(wt, v2.x, a2.x); a2.y = fmaf(wt, v2.y, a2.y);
        a2.z = fmaf(wt, v2.z, a2.z); a2.w = fmaf(wt, v2.w, a2.w);
        a3.x = fmaf(wt, v3.x, a3.x); a3.y = fmaf(wt, v3.y, a3.y);
        a3.z = fmaf(wt, v3.z, a3.z); a3.w = fmaf(wt, v3.w, a3.w);
    }
    __nv_bfloat162 h[8];
    h[0] = __float22bfloat162_rn(make_float2(a0.x, a0.y));
    h[1] = __float22bfloat162_rn(make_float2(a0.z, a0.w));
    h[2] = __float22bfloat162_rn(make_float2(a1.x, a1.y));
    h[3] = __float22bfloat162_rn(make_float2(a1.z, a1.w));
    h[4] = __float22bfloat162_rn(make_float2(a2.x, a2.y));
    h[5] = __float22bfloat162_rn(make_float2(a2.z, a2.w));
    h[6] = __float22bfloat162_rn(make_float2(a3.x, a3.y));
    h[7] = __float22bfloat162_rn(make_float2(a3.z, a3.w));
    __nv_bfloat16* o = g_outh + (size_t)token * VALUE_DIM + lane * 16;
    *(uint4*)o       = *(uint4*)(h);
    *(uint4*)(o + 8) = *(uint4*)(h + 4);
}

// ---------------- LayerNorm ---------------------------------------------------
__global__ __launch_bounds__(256) void ln_kernel(
    const float* __restrict__ gamma, const float* __restrict__ beta,
    float* __restrict__ out)
{
    const int row = blockIdx.x;
    const int tid = threadIdx.x;
    const float* yr = g_y + (size_t)row * D_MODEL;

    float v[4];
    float s = 0.f, ss = 0.f;
#pragma unroll
    for (int j = 0; j < 4; j++) {
        v[j] = yr[tid + 256 * j];
        s += v[j]; ss += v[j] * v[j];
    }
#pragma unroll
    for (int off = 16; off > 0; off >>= 1) {
        s  += __shfl_xor_sync(0xffffffffu, s, off);
        ss += __shfl_xor_sync(0xffffffffu, ss, off);
    }
    __shared__ float red_s[8], red_ss[8], s_mu, s_rstd;
    const int wid = tid >> 5, lane = tid & 31;
    if (lane == 0) { red_s[wid] = s; red_ss[wid] = ss; }
    __syncthreads();
    if (tid == 0) {
        float S = 0.f, SS = 0.f;
#pragma unroll
        for (int i = 0; i < 8; i++) { S += red_s[i]; SS += red_ss[i]; }
        float mu = S * (1.f / D_MODEL);
        s_mu = mu;
        s_rstd = rsqrtf(SS * (1.f / D_MODEL) - mu * mu + LN_EPS);
    }
    __syncthreads();
    const float mu = s_mu, rstd = s_rstd;
    float* orow = out + (size_t)row * D_MODEL;
#pragma unroll
    for (int j = 0; j < 4; j++) {
        int c = tid + 256 * j;
        orow[c] = (v[j] - mu) * rstd * gamma[c] + beta[c];
    }
}

// ---------------- launch ------------------------------------------------------
extern "C" void kernel_launch(void* const* d_in, const int* in_sizes, int n_in,
                              void* d_out, int out_size)
{
    const float* x      = (const float*)d_in[0];
    const float* Wq     = (const float*)d_in[1];
    const float* bq     = (const float*)d_in[2];
    const float* ca     = (const float*)d_in[3];
    const float* cb     = (const float*)d_in[4];
    const float* values = (const float*)d_in[5];
    const float* Wo     = (const float*)d_in[6];
    const float* bo     = (const float*)d_in[7];
    const float* gamma  = (const float*)d_in[8];
    const float* beta   = (const float*)d_in[9];
    float* out = (float*)d_out;

    const int NT = in_sizes[0] / D_MODEL;   // 8192

    __nv_bfloat16 *xh, *cah, *cbh, *wqT, *woT;
    cudaGetSymbolAddress((void**)&xh,  g_xh);
    cudaGetSymbolAddress((void**)&cah, g_cah);
    cudaGetSymbolAddress((void**)&cbh, g_cbh);
    cudaGetSymbolAddress((void**)&wqT, g_wqT);
    cudaGetSymbolAddress((void**)&woT, g_woT);

    // bf16 conversions + weight transposes
    k_cvt<<<dim3((NT * D_MODEL) / (256 * 8)), 256>>>(x, xh, NT * D_MODEL);
    k_cvt<<<dim3((SUB_KEYS * KEY_DIM) / (256 * 8)), 256>>>(ca, cah, SUB_KEYS * KEY_DIM);
    k_cvt<<<dim3((SUB_KEYS * KEY_DIM) / (256 * 8)), 256>>>(cb, cbh, SUB_KEYS * KEY_DIM);
    k_tr<<<dim3(2 * KEY_DIM / 32, D_MODEL / 32), dim3(32, 8)>>>(Wq, wqT, D_MODEL, 2 * KEY_DIM);
    k_tr<<<dim3(D_MODEL / 32, VALUE_DIM / 32), dim3(32, 8)>>>(Wo, woT, VALUE_DIM, D_MODEL);

    // q = x @ Wq + bq  (bf16 out)
    k_gemm_q<<<dim3(2 * KEY_DIM / 128, NT / 128), 256>>>(bq);
    // scores (fp32 out)
    k_gemm_sa<<<dim3(SUB_KEYS / 128, NT / 128), 256>>>();
    k_gemm_sb<<<dim3(SUB_KEYS / 128, NT / 128), 256>>>();
    // top-k + softmax + gather
    topk_gather_kernel<<<dim3((NT + 7) / 8), 256>>>(values, NT);
    // y = x + out @ Wo + bo
    k_gemm_y<<<dim3(D_MODEL / 128, NT / 128), 256>>>(bo, x);
    // LayerNorm
    ln_kernel<<<dim3(NT), 256>>>(gamma, beta, out);
}